// round 11
// baseline (speedup 1.0000x reference)
#include <cuda_runtime.h>
#include <cuda_bf16.h>

// CumAvgPool1d: y[..., t] = cumsum(x)[..., t] / (t+1)
// x: (8, 512, 16384) fp32 -> 4096 rows of T=16384.
//
// R10: CTA-per-row, 8 warps, 512-elem chunks, hardware-barrier relay.
// Row = 32 chunks of 512; round k = chunks 8k..8k+7, one per warp; 4 rounds.
// Per chunk a lane owns 4 float4 at 4 sector-perfect 512B segments; 4-way
// interleaved shuffle scans. Each warp publishes its chunk TOTAL to smem,
// one __syncthreads per round (publish drain included), then totals are
// combined with a 3-step width-8 shuffle scan. vs R9: the ballot spin-loop
// software barrier and per-256-elem overheads are gone -- ~2.5x fewer
// sync/loop instructions per byte. Depth-2 round prefetch ring keeps
// 8 LDG.128/lane in flight. Streaming hints (zero reuse).

constexpr int T_LEN  = 16384;
constexpr int T_F4   = T_LEN / 4;          // 4096 float4 per row
constexpr int CHUNK_F4 = 128;              // 512 elems per chunk
constexpr int CHUNKS = T_F4 / CHUNK_F4;    // 32
constexpr int WARPS  = 8;
constexpr int THREADS = WARPS * 32;        // 256
constexpr int ROUNDS = CHUNKS / WARPS;     // 4

__global__ void __launch_bounds__(THREADS)
cumavg_kernel(const float4* __restrict__ x, float4* __restrict__ y)
{
    __shared__ float relay[CHUNKS];

    const int tid  = threadIdx.x;
    const int lane = tid & 31;
    const int warp = tid >> 5;
    const int row  = blockIdx.x;

    const float4* px = x + (size_t)row * T_F4;
    float4*       py = y + (size_t)row * T_F4;

    // depth-2 prefetch ring over rounds: buffers for rounds k, k+1
    float4 buf[2][4];
    {
        const int c0 = warp;               // round 0 chunk
        const int c1 = warp + WARPS;       // round 1 chunk
        #pragma unroll
        for (int s = 0; s < 4; ++s) {
            buf[0][s] = __ldcs(px + c0 * CHUNK_F4 + s * 32 + lane);
            buf[1][s] = __ldcs(px + c1 * CHUNK_F4 + s * 32 + lane);
        }
    }

    float carry = 0.0f;
    // divisor base (exact integer floats): chunk c => t0 = c*512 + lane*4
    float tb = (float)(warp * 512 + lane * 4);

    #pragma unroll
    for (int k = 0; k < ROUNDS; ++k) {
        const int c = warp + WARPS * k;

        float4 v0 = buf[k & 1][0];
        float4 v1 = buf[k & 1][1];
        float4 v2 = buf[k & 1][2];
        float4 v3 = buf[k & 1][3];
        if (k + 2 < ROUNDS) {
            const int cn = c + 2 * WARPS;
            #pragma unroll
            for (int s = 0; s < 4; ++s)
                buf[k & 1][s] = __ldcs(px + cn * CHUNK_F4 + s * 32 + lane);
        }

        // four independent local scans (4 elems each)
        float r0 = v0.x; v0.x = r0; r0 += v0.y; v0.y = r0; r0 += v0.z; v0.z = r0; r0 += v0.w; v0.w = r0;
        float r1 = v1.x; v1.x = r1; r1 += v1.y; v1.y = r1; r1 += v1.z; v1.z = r1; r1 += v1.w; v1.w = r1;
        float r2 = v2.x; v2.x = r2; r2 += v2.y; v2.y = r2; r2 += v2.z; v2.z = r2; r2 += v2.w; v2.w = r2;
        float r3 = v3.x; v3.x = r3; r3 += v3.y; v3.y = r3; r3 += v3.z; v3.z = r3; r3 += v3.w; v3.w = r3;

        // four interleaved warp scans (ILP 4)
        float w0 = r0, w1 = r1, w2 = r2, w3 = r3;
        #pragma unroll
        for (int d = 1; d < 32; d <<= 1) {
            float n0 = __shfl_up_sync(0xffffffffu, w0, d);
            float n1 = __shfl_up_sync(0xffffffffu, w1, d);
            float n2 = __shfl_up_sync(0xffffffffu, w2, d);
            float n3 = __shfl_up_sync(0xffffffffu, w3, d);
            if (lane >= d) { w0 += n0; w1 += n1; w2 += n2; w3 += n3; }
        }

        const float T0 = __shfl_sync(0xffffffffu, w0, 31);
        const float T1 = __shfl_sync(0xffffffffu, w1, 31);
        const float T2 = __shfl_sync(0xffffffffu, w2, 31);
        const float T3 = __shfl_sync(0xffffffffu, w3, 31);

        // publish chunk total; HW barrier makes it visible to all warps
        if (lane == 0) relay[c] = T0 + T1 + T2 + T3;
        __syncthreads();

        // combine the round's 8 totals: width-8 inclusive shuffle scan
        float s = relay[WARPS * k + (lane & (WARPS - 1))];
        #pragma unroll
        for (int d = 1; d < WARPS; d <<= 1) {
            float n = __shfl_up_sync(0xffffffffu, s, d, WARPS);
            if ((lane & (WARPS - 1)) >= d) s += n;
        }
        const float all = __shfl_sync(0xffffffffu, s, WARPS - 1, WARPS);
        const float pw  = __shfl_sync(0xffffffffu, s, (warp == 0 ? 0 : warp - 1), WARPS);
        const float P   = carry + (warp ? pw : 0.0f);
        carry += all;

        // per-segment exclusive offsets
        const float o0 = P + (w0 - r0);
        const float o1 = P + T0 + (w1 - r1);
        const float o2 = P + T0 + T1 + (w2 - r2);
        const float o3 = P + T0 + T1 + T2 + (w3 - r3);

        // y[t] = (off + local) / (t+1); divisors via float adds (exact ints)
        float4 o;
        o.x = (o0 + v0.x) * __fdividef(1.0f, tb + 1.0f);
        o.y = (o0 + v0.y) * __fdividef(1.0f, tb + 2.0f);
        o.z = (o0 + v0.z) * __fdividef(1.0f, tb + 3.0f);
        o.w = (o0 + v0.w) * __fdividef(1.0f, tb + 4.0f);
        __stcs(py + c * CHUNK_F4 + lane, o);

        o.x = (o1 + v1.x) * __fdividef(1.0f, tb + 129.0f);
        o.y = (o1 + v1.y) * __fdividef(1.0f, tb + 130.0f);
        o.z = (o1 + v1.z) * __fdividef(1.0f, tb + 131.0f);
        o.w = (o1 + v1.w) * __fdividef(1.0f, tb + 132.0f);
        __stcs(py + c * CHUNK_F4 + 32 + lane, o);

        o.x = (o2 + v2.x) * __fdividef(1.0f, tb + 257.0f);
        o.y = (o2 + v2.y) * __fdividef(1.0f, tb + 258.0f);
        o.z = (o2 + v2.z) * __fdividef(1.0f, tb + 259.0f);
        o.w = (o2 + v2.w) * __fdividef(1.0f, tb + 260.0f);
        __stcs(py + c * CHUNK_F4 + 64 + lane, o);

        o.x = (o3 + v3.x) * __fdividef(1.0f, tb + 385.0f);
        o.y = (o3 + v3.y) * __fdividef(1.0f, tb + 386.0f);
        o.z = (o3 + v3.z) * __fdividef(1.0f, tb + 387.0f);
        o.w = (o3 + v3.w) * __fdividef(1.0f, tb + 388.0f);
        __stcs(py + c * CHUNK_F4 + 96 + lane, o);

        tb += (float)(WARPS * 512);   // next owned chunk is 4096 elems ahead
    }
}

extern "C" void kernel_launch(void* const* d_in, const int* in_sizes, int n_in,
                              void* d_out, int out_size)
{
    const float* x = (const float*)d_in[0];
    float*       y = (float*)d_out;
    const int total = in_sizes[0];
    const int rows  = total / T_LEN;   // 4096 for the reference shape

    cumavg_kernel<<<rows, THREADS>>>((const float4*)x, (float4*)y);
}

// round 12
// speedup vs baseline: 1.0499x; 1.0499x over previous
#include <cuda_runtime.h>
#include <cuda_bf16.h>

// CumAvgPool1d: y[..., t] = cumsum(x)[..., t] / (t+1)
// x: (8, 512, 16384) fp32 -> 4096 rows of T=16384.
//
// R11: R9's layout (CTA-per-row, 8 warps, 256-elem chunks, depth-2 ring,
// ~48 regs -> high occupancy) with R10's cheap synchronization: per round,
// each warp STS's its chunk TOTAL, one hardware __syncthreads, then a
// width-8 shuffle scan combines the 8 totals (replaces R9's ballot
// spin-loop + 8-shuffle gather: ~35 -> ~12 instrs per chunk).
// 8 rounds/row, 8 barriers/row (~10-30cyc each, negligible).
// Loads/stores sector-perfect 512B per instruction; streaming hints.

constexpr int T_LEN  = 16384;
constexpr int T_F4   = T_LEN / 4;          // 4096 float4 per row
constexpr int CHUNK_F4 = 64;               // 256 elems per chunk
constexpr int CHUNKS = T_F4 / CHUNK_F4;    // 64
constexpr int WARPS  = 8;
constexpr int THREADS = WARPS * 32;        // 256
constexpr int ROUNDS = CHUNKS / WARPS;     // 8

__global__ void __launch_bounds__(THREADS)
cumavg_kernel(const float4* __restrict__ x, float4* __restrict__ y)
{
    __shared__ float relay[CHUNKS];

    const int tid  = threadIdx.x;
    const int lane = tid & 31;
    const int warp = tid >> 5;
    const int row  = blockIdx.x;

    const float4* px = x + (size_t)row * T_F4;
    float4*       py = y + (size_t)row * T_F4;

    // depth-2 prefetch ring over this warp's chunks (w, w+8, w+16, ...)
    float4 ra4[2], rb4[2];
    {
        const int c0 = warp;
        const int c1 = warp + WARPS;
        ra4[0] = __ldcs(px + c0 * CHUNK_F4 + lane);
        rb4[0] = __ldcs(px + c0 * CHUNK_F4 + 32 + lane);
        ra4[1] = __ldcs(px + c1 * CHUNK_F4 + lane);
        rb4[1] = __ldcs(px + c1 * CHUNK_F4 + 32 + lane);
    }

    float carry = 0.0f;
    // divisor base (exact integer floats): chunk c => t0 = c*256 + lane*4
    float tb = (float)(warp * 256 + lane * 4);

    #pragma unroll 2
    for (int k = 0; k < ROUNDS; ++k) {
        const int c = warp + WARPS * k;

        float4 a = ra4[k & 1];
        float4 b = rb4[k & 1];
        if (k + 2 < ROUNDS) {
            const int cn = c + 2 * WARPS;
            ra4[k & 1] = __ldcs(px + cn * CHUNK_F4 + lane);
            rb4[k & 1] = __ldcs(px + cn * CHUNK_F4 + 32 + lane);
        }

        // two independent local scans (4 elems each)
        float rA = a.x;  a.x = rA;
        rA += a.y;       a.y = rA;
        rA += a.z;       a.z = rA;
        rA += a.w;       a.w = rA;

        float rB = b.x;  b.x = rB;
        rB += b.y;       b.y = rB;
        rB += b.z;       b.z = rB;
        rB += b.w;       b.w = rB;

        // two interleaved warp scans (ILP 2)
        float wA = rA, wB = rB;
        #pragma unroll
        for (int d = 1; d < 32; d <<= 1) {
            float nA = __shfl_up_sync(0xffffffffu, wA, d);
            float nB = __shfl_up_sync(0xffffffffu, wB, d);
            if (lane >= d) { wA += nA; wB += nB; }
        }

        const float totalA = __shfl_sync(0xffffffffu, wA, 31);
        const float totalB = __shfl_sync(0xffffffffu, wB, 31);

        // publish chunk total; HW barrier publishes across warps
        if (lane == 0) relay[c] = totalA + totalB;
        __syncthreads();

        // combine the round's 8 totals: width-8 inclusive shuffle scan
        float s = relay[WARPS * k + (lane & (WARPS - 1))];
        #pragma unroll
        for (int d = 1; d < WARPS; d <<= 1) {
            float n = __shfl_up_sync(0xffffffffu, s, d, WARPS);
            if ((lane & (WARPS - 1)) >= d) s += n;
        }
        const float all = __shfl_sync(0xffffffffu, s, WARPS - 1, WARPS);
        const float pw  = __shfl_sync(0xffffffffu, s, (warp == 0 ? 0 : warp - 1), WARPS);
        const float P   = carry + (warp ? pw : 0.0f);
        carry += all;

        const float offA = P + (wA - rA);            // exclusive prefix, A half
        const float offB = P + totalA + (wB - rB);   // exclusive prefix, B half

        // y[t] = (off + local) / (t+1); divisors via float adds (exact ints)
        float4 o;
        o.x = (offA + a.x) * __fdividef(1.0f, tb + 1.0f);
        o.y = (offA + a.y) * __fdividef(1.0f, tb + 2.0f);
        o.z = (offA + a.z) * __fdividef(1.0f, tb + 3.0f);
        o.w = (offA + a.w) * __fdividef(1.0f, tb + 4.0f);
        __stcs(py + c * CHUNK_F4 + lane, o);

        o.x = (offB + b.x) * __fdividef(1.0f, tb + 129.0f);
        o.y = (offB + b.y) * __fdividef(1.0f, tb + 130.0f);
        o.z = (offB + b.z) * __fdividef(1.0f, tb + 131.0f);
        o.w = (offB + b.w) * __fdividef(1.0f, tb + 132.0f);
        __stcs(py + c * CHUNK_F4 + 32 + lane, o);

        tb += (float)(WARPS * 256);   // next owned chunk is 2048 elems ahead
    }
}

extern "C" void kernel_launch(void* const* d_in, const int* in_sizes, int n_in,
                              void* d_out, int out_size)
{
    const float* x = (const float*)d_in[0];
    float*       y = (float*)d_out;
    const int total = in_sizes[0];
    const int rows  = total / T_LEN;   // 4096 for the reference shape

    cumavg_kernel<<<rows, THREADS>>>((const float4*)x, (float4*)y);
}